// round 15
// baseline (speedup 1.0000x reference)
#include <cuda_runtime.h>
#include <cuda_fp16.h>
#include <cstdint>

#define D_F 16

// ---- global prepped weight image (fp16, hi-only, compact) ----
// Per field d (1024 B at d*1024):
//   +0    : W1, 2 tiles 8x8 f16 [n0-7][n8-15]; row=n, col=k: k<3 -> W1[d][n][k],
//           k==3 -> b1[d][n], else 0
//   +256  : W2, 4 tiles {(n0,k0),(n0,k1),(n1,k0),(n1,k1)}; W2[d][g][h]
//   +768  : W3, 2 tiles [k0][k1]; row=o (0 pad o>=3), col=h   (used as A m0k0/m0k8)
// B2 at 16384: u32[16][8]  packed f16x2 pairs (b2[d][2j], b2[d][2j+1])
// B3 at 16896: f32[16][8]  b3[d][o] (0 pad o>=3)
#define B2_OFF 16384
#define B3_OFF 16896
#define IMG_BYTES 17408

__device__ __align__(16) unsigned char g_img[IMG_BYTES];

// ============ prep kernel ============
__global__ void prep_kernel(const float* __restrict__ W1, const float* __restrict__ b1,
                            const float* __restrict__ W2, const float* __restrict__ b2,
                            const float* __restrict__ W3, const float* __restrict__ b3)
{
    int i = blockIdx.x * blockDim.x + threadIdx.x;
    unsigned short* wimg = (unsigned short*)g_img;
    if (i < 8192) {                       // 16 fields x 512 hi entries
        int d = i >> 9;
        int w = i & 511;
        int fb = d * 512;
        float v = 0.0f;
        if (w < 128) {                    // W1 (+ b1 in k=3 column)
            int s = w, tile = s >> 6, rr = (s >> 3) & 7, cc = s & 7;
            int n = tile * 8 + rr;
            if (cc < 3)       v = W1[d * 48 + n * 3 + cc];
            else if (cc == 3) v = b1[d * 16 + n];
        } else if (w < 384) {             // W2
            int s = w - 128, tt = s >> 6, rr = (s >> 3) & 7, cc = s & 7;
            int nt = tt >> 1, kt = tt & 1;
            v = W2[d * 256 + (nt * 8 + rr) * 16 + (kt * 8 + cc)];
        } else {                          // W3
            int s = w - 384, kt = s >> 6, rr = (s >> 3) & 7, cc = s & 7;
            v = (rr < 3) ? W3[d * 48 + rr * 16 + (kt * 8 + cc)] : 0.0f;
        }
        __half hv = __float2half_rn(v);
        wimg[fb + w] = reinterpret_cast<unsigned short&>(hv);
    } else if (i < 8192 + 128) {          // b2 packed f16x2 pairs
        int j = i - 8192;
        int d = j >> 3, pr = j & 7;
        __half h0 = __float2half_rn(b2[d * 16 + 2 * pr]);
        __half h1 = __float2half_rn(b2[d * 16 + 2 * pr + 1]);
        unsigned u0 = reinterpret_cast<unsigned short&>(h0);
        unsigned u1 = reinterpret_cast<unsigned short&>(h1);
        ((unsigned*)(g_img + B2_OFF))[j] = u0 | (u1 << 16);
    } else if (i < 8192 + 128 + 128) {    // b3 padded f32
        int j = i - 8320;
        int d = j >> 3, o = j & 7;
        ((float*)(g_img + B3_OFF))[j] = (o < 3) ? b3[d * 3 + o] : 0.0f;
    }
}

// ============ mma / cvt helpers ============
__device__ __forceinline__ void ldsm4(unsigned& r0, unsigned& r1, unsigned& r2, unsigned& r3,
                                      unsigned a) {
    asm volatile("ldmatrix.sync.aligned.m8n8.x4.shared.b16 {%0,%1,%2,%3}, [%4];"
                 : "=r"(r0), "=r"(r1), "=r"(r2), "=r"(r3) : "r"(a));
}
__device__ __forceinline__ void ldsm2(unsigned& r0, unsigned& r1, unsigned a) {
    asm volatile("ldmatrix.sync.aligned.m8n8.x2.shared.b16 {%0,%1}, [%2];"
                 : "=r"(r0), "=r"(r1) : "r"(a));
}
// f16-accumulator m16n8k8
__device__ __forceinline__ void mma_k8_h(unsigned d[2], unsigned a0, unsigned a1, unsigned b0,
                                         unsigned c0, unsigned c1) {
    asm volatile("mma.sync.aligned.m16n8k8.row.col.f16.f16.f16.f16 "
                 "{%0,%1}, {%2,%3}, {%4}, {%5,%6};"
                 : "=r"(d[0]), "=r"(d[1])
                 : "r"(a0), "r"(a1), "r"(b0), "r"(c0), "r"(c1));
}
// f16-accumulator m16n8k16
__device__ __forceinline__ void mma_k16_h(unsigned d[2], const unsigned a[4],
                                          unsigned b0, unsigned b1,
                                          unsigned c0, unsigned c1) {
    asm volatile("mma.sync.aligned.m16n8k16.row.col.f16.f16.f16.f16 "
                 "{%0,%1}, {%2,%3,%4,%5}, {%6,%7}, {%8,%9};"
                 : "=r"(d[0]), "=r"(d[1])
                 : "r"(a[0]), "r"(a[1]), "r"(a[2]), "r"(a[3]),
                   "r"(b0), "r"(b1), "r"(c0), "r"(c1));
}
// f32-accumulator m16n8k16 (layer 3, transposed: A=W3, B=h2 frags)
__device__ __forceinline__ void mma_k16(float c[4], const unsigned a[4], unsigned b0, unsigned b1) {
    asm volatile("mma.sync.aligned.m16n8k16.row.col.f32.f16.f16.f32 "
                 "{%0,%1,%2,%3}, {%4,%5,%6,%7}, {%8,%9}, {%0,%1,%2,%3};"
                 : "+f"(c[0]), "+f"(c[1]), "+f"(c[2]), "+f"(c[3])
                 : "r"(a[0]), "r"(a[1]), "r"(a[2]), "r"(a[3]), "r"(b0), "r"(b1));
}
__device__ __forceinline__ unsigned cvt2(float v0, float v1) {
    unsigned h;
    asm("cvt.rn.f16x2.f32 %0, %1, %2;" : "=r"(h) : "f"(v1), "f"(v0));
    return h;
}
__device__ __forceinline__ unsigned relu2h(unsigned v) {
    unsigned r;
    asm("max.f16x2 %0, %1, %2;" : "=r"(r) : "r"(v), "r"(0u));
    return r;
}

// ============ main kernel: 3 point-tiles (48 pts), transposed l3, STG.64 ============
__global__ __launch_bounds__(128, 9)
void fields_mma_kernel(const float* __restrict__ x, float* __restrict__ out, int N)
{
    __shared__ __align__(16) unsigned char smem[IMG_BYTES];
    {
        const uint4* src = (const uint4*)g_img;
        uint4* dst = (uint4*)smem;
        for (int i = threadIdx.x; i < IMG_BYTES / 16; i += blockDim.x) dst[i] = src[i];
    }
    __syncthreads();

    const unsigned sbase = (unsigned)__cvta_generic_to_shared(smem);
    const unsigned* sB2 = (const unsigned*)(smem + B2_OFF);
    const float*    sB3 = (const float*)(smem + B3_OFF);

    const int tid  = threadIdx.x;
    const int wid  = tid >> 5, lane = tid & 31;
    const int q    = lane & 3, r = lane >> 2;
    const unsigned lm_off = ((unsigned)(lane >> 3) << 7) + ((unsigned)(lane & 7) << 4);

    const int gwarp  = blockIdx.x * 4 + wid;
    const int nwarps = gridDim.x * 4;
    const int ntiles = (N + 47) / 48;            // 48 points per tile

    for (int tile = gwarp; tile < ntiles; tile += nwarps) {
        const int P = tile * 48;
        const int pA0 = P + r,      pA1 = P + r + 8;
        const int pB0 = P + r + 16, pB1 = P + r + 24;
        const int pC0 = P + r + 32, pC1 = P + r + 40;
        const bool iA0 = pA0 < N, iA1 = pA1 < N, iB0 = pB0 < N, iB1 = pB1 < N;
        const bool iC0 = pC0 < N, iC1 = pC1 < N;

        // ---- x A-fragments (single fp16): k = {x0,x1,x2,1,0,0,0,0} ----
        float a00 = 0.f, a01 = 0.f, a10 = 0.f, a11 = 0.f;
        float b00 = 0.f, b01 = 0.f, b10 = 0.f, b11 = 0.f;
        float c00 = 0.f, c01 = 0.f, c10 = 0.f, c11 = 0.f;
        if (q == 0) {
            if (iA0) { a00 = x[pA0]; a01 = x[N + pA0]; }
            if (iA1) { a10 = x[pA1]; a11 = x[N + pA1]; }
            if (iB0) { b00 = x[pB0]; b01 = x[N + pB0]; }
            if (iB1) { b10 = x[pB1]; b11 = x[N + pB1]; }
            if (iC0) { c00 = x[pC0]; c01 = x[N + pC0]; }
            if (iC1) { c10 = x[pC1]; c11 = x[N + pC1]; }
        } else if (q == 1) {
            if (iA0) { a00 = x[2 * N + pA0]; a01 = 1.0f; }
            if (iA1) { a10 = x[2 * N + pA1]; a11 = 1.0f; }
            if (iB0) { b00 = x[2 * N + pB0]; b01 = 1.0f; }
            if (iB1) { b10 = x[2 * N + pB1]; b11 = 1.0f; }
            if (iC0) { c00 = x[2 * N + pC0]; c01 = 1.0f; }
            if (iC1) { c10 = x[2 * N + pC1]; c11 = 1.0f; }
        }
        const unsigned xA0 = cvt2(a00, a01), xA1 = cvt2(a10, a11);
        const unsigned xB0 = cvt2(b00, b01), xB1 = cvt2(b10, b11);
        const unsigned xC0 = cvt2(c00, c01), xC1 = cvt2(c10, c11);

        #pragma unroll 1
        for (int d = 0; d < D_F; d++) {
            const unsigned fbase = sbase + (unsigned)(d * 1024);

            // ================= layer 1 (f16 accum; bias via x k=3 column) =========
            unsigned w1h0, w1h1;
            ldsm2(w1h0, w1h1, fbase + lm_off);
            unsigned cA0[2], cA1[2], cB0[2], cB1[2], cC0[2], cC1[2];
            mma_k8_h(cA0, xA0, xA1, w1h0, 0u, 0u);
            mma_k8_h(cB0, xB0, xB1, w1h0, 0u, 0u);
            mma_k8_h(cC0, xC0, xC1, w1h0, 0u, 0u);
            mma_k8_h(cA1, xA0, xA1, w1h1, 0u, 0u);
            mma_k8_h(cB1, xB0, xB1, w1h1, 0u, 0u);
            mma_k8_h(cC1, xC0, xC1, w1h1, 0u, 0u);

            unsigned aA[4], aB[4], aC[4];
            aA[0] = relu2h(cA0[0]);  aA[1] = relu2h(cA0[1]);
            aA[2] = relu2h(cA1[0]);  aA[3] = relu2h(cA1[1]);
            aB[0] = relu2h(cB0[0]);  aB[1] = relu2h(cB0[1]);
            aB[2] = relu2h(cB1[0]);  aB[3] = relu2h(cB1[1]);
            aC[0] = relu2h(cC0[0]);  aC[1] = relu2h(cC0[1]);
            aC[2] = relu2h(cC1[0]);  aC[3] = relu2h(cC1[1]);

            // ================= layer 2 (f16 accum; pre-packed f16x2 bias) =========
            unsigned w2h0, w2h1, w2h2, w2h3;
            ldsm4(w2h0, w2h1, w2h2, w2h3, fbase + 256 + lm_off);
            const unsigned bh0 = sB2[d * 8 + q];        // cols 2q,2q+1
            const unsigned bh1 = sB2[d * 8 + 4 + q];    // cols 2q+8,2q+9

            unsigned eA0[2], eA1[2], eB0[2], eB1[2], eC0[2], eC1[2];
            mma_k16_h(eA0, aA, w2h0, w2h1, bh0, bh0);
            mma_k16_h(eB0, aB, w2h0, w2h1, bh0, bh0);
            mma_k16_h(eC0, aC, w2h0, w2h1, bh0, bh0);
            mma_k16_h(eA1, aA, w2h2, w2h3, bh1, bh1);
            mma_k16_h(eB1, aB, w2h2, w2h3, bh1, bh1);
            mma_k16_h(eC1, aC, w2h2, w2h3, bh1, bh1);

            unsigned gA[4], gB[4], gC[4];
            gA[0] = relu2h(eA0[0]);  gA[1] = relu2h(eA0[1]);
            gA[2] = relu2h(eA1[0]);  gA[3] = relu2h(eA1[1]);
            gB[0] = relu2h(eB0[0]);  gB[1] = relu2h(eB0[1]);
            gB[2] = relu2h(eB1[0]);  gB[3] = relu2h(eB1[1]);
            gC[0] = relu2h(eC0[0]);  gC[1] = relu2h(eC0[1]);
            gC[2] = relu2h(eC1[0]);  gC[3] = relu2h(eC1[1]);

            // ========== layer 3 TRANSPOSED: A=W3 (rows=o), B=g frags (cols=points) =
            // g[0],g[2] is exactly the B fragment for points base+0..7 (n=r, k=2q,2q+1);
            // g[1],g[3] for points base+8..15. C: lane(q,r) holds (o=r, pts 2q,2q+1).
            unsigned w3t0, w3t1;
            ldsm2(w3t0, w3t1, fbase + 768 + lm_off);
            const unsigned w3a[4] = {w3t0, 0u, w3t1, 0u};   // rows 8-15 of o are zero
            const float bo = sB3[d * 8 + r];                // b3[d][o=r], 0-padded

            float* rp = out + (size_t)(d * 3 + r) * N;      // valid when r < 3

            // sub-tile A (points P .. P+15)
            {
                float fL[4] = {bo, bo, bo, bo};
                mma_k16(fL, w3a, gA[0], gA[2]);
                float fH[4] = {bo, bo, bo, bo};
                mma_k16(fH, w3a, gA[1], gA[3]);
                if (r < 3) {
                    int p0 = P + 2 * q;
                    if (p0 + 1 < N) *(float2*)(rp + p0) = make_float2(fL[0], fL[1]);
                    int p1 = P + 8 + 2 * q;
                    if (p1 + 1 < N) *(float2*)(rp + p1) = make_float2(fH[0], fH[1]);
                }
            }
            // sub-tile B (points P+16 .. P+31)
            {
                float fL[4] = {bo, bo, bo, bo};
                mma_k16(fL, w3a, gB[0], gB[2]);
                float fH[4] = {bo, bo, bo, bo};
                mma_k16(fH, w3a, gB[1], gB[3]);
                if (r < 3) {
                    int p0 = P + 16 + 2 * q;
                    if (p0 + 1 < N) *(float2*)(rp + p0) = make_float2(fL[0], fL[1]);
                    int p1 = P + 24 + 2 * q;
                    if (p1 + 1 < N) *(float2*)(rp + p1) = make_float2(fH[0], fH[1]);
                }
            }
            // sub-tile C (points P+32 .. P+47)
            {
                float fL[4] = {bo, bo, bo, bo};
                mma_k16(fL, w3a, gC[0], gC[2]);
                float fH[4] = {bo, bo, bo, bo};
                mma_k16(fH, w3a, gC[1], gC[3]);
                if (r < 3) {
                    int p0 = P + 32 + 2 * q;
                    if (p0 + 1 < N) *(float2*)(rp + p0) = make_float2(fL[0], fL[1]);
                    int p1 = P + 40 + 2 * q;
                    if (p1 + 1 < N) *(float2*)(rp + p1) = make_float2(fH[0], fH[1]);
                }
            }
        }
    }
}

extern "C" void kernel_launch(void* const* d_in, const int* in_sizes, int n_in,
                              void* d_out, int out_size)
{
    const float* x  = (const float*)d_in[0];
    const float* W1 = (const float*)d_in[1];
    const float* b1 = (const float*)d_in[2];
    const float* W2 = (const float*)d_in[3];
    const float* b2 = (const float*)d_in[4];
    const float* W3 = (const float*)d_in[5];
    const float* b3 = (const float*)d_in[6];
    float* out = (float*)d_out;

    const int N = in_sizes[0] / 3;   // x is [1,3,N]

    prep_kernel<<<(8448 + 255) / 256, 256>>>(W1, b1, W2, b2, W3, b3);

    // 9 CTAs/SM x 128 threads on 152 SMs = 1368 CTAs, one clean wave
    fields_mma_kernel<<<1368, 128>>>(x, out, N);
}

// round 16
// speedup vs baseline: 1.1290x; 1.1290x over previous
#include <cuda_runtime.h>
#include <cuda_fp16.h>
#include <cstdint>

#define D_F 16

// ---- global prepped weight image (fp16, hi-only, compact) ----
// Per field d (1024 B at d*1024):
//   +0    : W1, 2 tiles 8x8 f16 [n0-7][n8-15]; row=n, col=k: k<3 -> W1[d][n][k],
//           k==3 -> b1[d][n], else 0
//   +256  : W2, 4 tiles {(n0,k0),(n0,k1),(n1,k0),(n1,k1)}; W2[d][g][h]
//   +768  : W3, 2 tiles [k0][k1]; row=o (0 pad o>=3), col=h   (used as A of l3)
// B2 at 16384: u32[16][8]  packed f16x2 pairs (b2[d][2j], b2[d][2j+1])
// B3 at 16896: f32[16][8]  b3[d][o] (0 pad o>=3)
#define B2_OFF 16384
#define B3_OFF 16896
#define IMG_BYTES 17408

__device__ __align__(16) unsigned char g_img[IMG_BYTES];

// ============ prep kernel ============
__global__ void prep_kernel(const float* __restrict__ W1, const float* __restrict__ b1,
                            const float* __restrict__ W2, const float* __restrict__ b2,
                            const float* __restrict__ W3, const float* __restrict__ b3)
{
    int i = blockIdx.x * blockDim.x + threadIdx.x;
    unsigned short* wimg = (unsigned short*)g_img;
    if (i < 8192) {                       // 16 fields x 512 hi entries
        int d = i >> 9;
        int w = i & 511;
        int fb = d * 512;
        float v = 0.0f;
        if (w < 128) {                    // W1 (+ b1 in k=3 column)
            int s = w, tile = s >> 6, rr = (s >> 3) & 7, cc = s & 7;
            int n = tile * 8 + rr;
            if (cc < 3)       v = W1[d * 48 + n * 3 + cc];
            else if (cc == 3) v = b1[d * 16 + n];
        } else if (w < 384) {             // W2
            int s = w - 128, tt = s >> 6, rr = (s >> 3) & 7, cc = s & 7;
            int nt = tt >> 1, kt = tt & 1;
            v = W2[d * 256 + (nt * 8 + rr) * 16 + (kt * 8 + cc)];
        } else {                          // W3
            int s = w - 384, kt = s >> 6, rr = (s >> 3) & 7, cc = s & 7;
            v = (rr < 3) ? W3[d * 48 + rr * 16 + (kt * 8 + cc)] : 0.0f;
        }
        __half hv = __float2half_rn(v);
        wimg[fb + w] = reinterpret_cast<unsigned short&>(hv);
    } else if (i < 8192 + 128) {          // b2 packed f16x2 pairs
        int j = i - 8192;
        int d = j >> 3, pr = j & 7;
        __half h0 = __float2half_rn(b2[d * 16 + 2 * pr]);
        __half h1 = __float2half_rn(b2[d * 16 + 2 * pr + 1]);
        unsigned u0 = reinterpret_cast<unsigned short&>(h0);
        unsigned u1 = reinterpret_cast<unsigned short&>(h1);
        ((unsigned*)(g_img + B2_OFF))[j] = u0 | (u1 << 16);
    } else if (i < 8192 + 128 + 128) {    // b3 padded f32
        int j = i - 8320;
        int d = j >> 3, o = j & 7;
        ((float*)(g_img + B3_OFF))[j] = (o < 3) ? b3[d * 3 + o] : 0.0f;
    }
}

// ============ mma / cvt helpers ============
__device__ __forceinline__ void ldsm4(unsigned& r0, unsigned& r1, unsigned& r2, unsigned& r3,
                                      unsigned a) {
    asm volatile("ldmatrix.sync.aligned.m8n8.x4.shared.b16 {%0,%1,%2,%3}, [%4];"
                 : "=r"(r0), "=r"(r1), "=r"(r2), "=r"(r3) : "r"(a));
}
__device__ __forceinline__ void ldsm2(unsigned& r0, unsigned& r1, unsigned a) {
    asm volatile("ldmatrix.sync.aligned.m8n8.x2.shared.b16 {%0,%1}, [%2];"
                 : "=r"(r0), "=r"(r1) : "r"(a));
}
// f16-accumulator m16n8k8
__device__ __forceinline__ void mma_k8_h(unsigned d[2], unsigned a0, unsigned a1, unsigned b0,
                                         unsigned c0, unsigned c1) {
    asm volatile("mma.sync.aligned.m16n8k8.row.col.f16.f16.f16.f16 "
                 "{%0,%1}, {%2,%3}, {%4}, {%5,%6};"
                 : "=r"(d[0]), "=r"(d[1])
                 : "r"(a0), "r"(a1), "r"(b0), "r"(c0), "r"(c1));
}
// f16-accumulator m16n8k16
__device__ __forceinline__ void mma_k16_h(unsigned d[2], const unsigned a[4],
                                          unsigned b0, unsigned b1,
                                          unsigned c0, unsigned c1) {
    asm volatile("mma.sync.aligned.m16n8k16.row.col.f16.f16.f16.f16 "
                 "{%0,%1}, {%2,%3,%4,%5}, {%6,%7}, {%8,%9};"
                 : "=r"(d[0]), "=r"(d[1])
                 : "r"(a[0]), "r"(a[1]), "r"(a[2]), "r"(a[3]),
                   "r"(b0), "r"(b1), "r"(c0), "r"(c1));
}
// f32-accumulator m16n8k16, C = 0 (layer 3 transposed; bias added after)
__device__ __forceinline__ void mma_k16_z(float d[4], const unsigned a[4],
                                          unsigned b0, unsigned b1) {
    asm volatile("mma.sync.aligned.m16n8k16.row.col.f32.f16.f16.f32 "
                 "{%0,%1,%2,%3}, {%4,%5,%6,%7}, {%8,%9}, {%10,%11,%12,%13};"
                 : "=f"(d[0]), "=f"(d[1]), "=f"(d[2]), "=f"(d[3])
                 : "r"(a[0]), "r"(a[1]), "r"(a[2]), "r"(a[3]), "r"(b0), "r"(b1),
                   "f"(0.0f), "f"(0.0f), "f"(0.0f), "f"(0.0f));
}
__device__ __forceinline__ unsigned cvt2(float v0, float v1) {
    unsigned h;
    asm("cvt.rn.f16x2.f32 %0, %1, %2;" : "=r"(h) : "f"(v1), "f"(v0));
    return h;
}
__device__ __forceinline__ unsigned relu2h(unsigned v) {
    unsigned r;
    asm("max.f16x2 %0, %1, %2;" : "=r"(r) : "r"(v), "r"(0u));
    return r;
}

// ============ main kernel: 3 point-tiles (48 pts), transposed l3, STG.64 ============
__global__ __launch_bounds__(128, 9)
void fields_mma_kernel(const float* __restrict__ x, float* __restrict__ out, int N)
{
    __shared__ __align__(16) unsigned char smem[IMG_BYTES];
    {
        const uint4* src = (const uint4*)g_img;
        uint4* dst = (uint4*)smem;
        for (int i = threadIdx.x; i < IMG_BYTES / 16; i += blockDim.x) dst[i] = src[i];
    }
    __syncthreads();

    const unsigned sbase = (unsigned)__cvta_generic_to_shared(smem);
    const unsigned* sB2 = (const unsigned*)(smem + B2_OFF);
    const float*    sB3 = (const float*)(smem + B3_OFF);

    const int tid  = threadIdx.x;
    const int wid  = tid >> 5, lane = tid & 31;
    const int q    = lane & 3, r = lane >> 2;
    const unsigned lm_off = ((unsigned)(lane >> 3) << 7) + ((unsigned)(lane & 7) << 4);

    const int gwarp  = blockIdx.x * 4 + wid;
    const int nwarps = gridDim.x * 4;
    const int ntiles = (N + 47) / 48;            // 48 points per tile

    for (int tile = gwarp; tile < ntiles; tile += nwarps) {
        const int P = tile * 48;
        const int pA0 = P + r,      pA1 = P + r + 8;
        const int pB0 = P + r + 16, pB1 = P + r + 24;
        const int pC0 = P + r + 32, pC1 = P + r + 40;
        const bool iA0 = pA0 < N, iA1 = pA1 < N, iB0 = pB0 < N, iB1 = pB1 < N;
        const bool iC0 = pC0 < N, iC1 = pC1 < N;

        // ---- hoisted store offsets + guards (d-invariant) ----
        const int s0 = P + 2 * q,  s1 = s0 + 8,  s2 = s0 + 16,
                  s3 = s0 + 24,   s4 = s0 + 32, s5 = s0 + 40;
        const bool wv = (r < 3);
        const bool t0 = wv && (s0 + 1 < N), t1 = wv && (s1 + 1 < N),
                   t2 = wv && (s2 + 1 < N), t3 = wv && (s3 + 1 < N),
                   t4 = wv && (s4 + 1 < N), t5 = wv && (s5 + 1 < N);

        // ---- x A-fragments (single fp16): k = {x0,x1,x2,1,0,0,0,0} ----
        float a00 = 0.f, a01 = 0.f, a10 = 0.f, a11 = 0.f;
        float b00 = 0.f, b01 = 0.f, b10 = 0.f, b11 = 0.f;
        float c00 = 0.f, c01 = 0.f, c10 = 0.f, c11 = 0.f;
        if (q == 0) {
            if (iA0) { a00 = x[pA0]; a01 = x[N + pA0]; }
            if (iA1) { a10 = x[pA1]; a11 = x[N + pA1]; }
            if (iB0) { b00 = x[pB0]; b01 = x[N + pB0]; }
            if (iB1) { b10 = x[pB1]; b11 = x[N + pB1]; }
            if (iC0) { c00 = x[pC0]; c01 = x[N + pC0]; }
            if (iC1) { c10 = x[pC1]; c11 = x[N + pC1]; }
        } else if (q == 1) {
            if (iA0) { a00 = x[2 * N + pA0]; a01 = 1.0f; }
            if (iA1) { a10 = x[2 * N + pA1]; a11 = 1.0f; }
            if (iB0) { b00 = x[2 * N + pB0]; b01 = 1.0f; }
            if (iB1) { b10 = x[2 * N + pB1]; b11 = 1.0f; }
            if (iC0) { c00 = x[2 * N + pC0]; c01 = 1.0f; }
            if (iC1) { c10 = x[2 * N + pC1]; c11 = 1.0f; }
        }
        const unsigned xA0 = cvt2(a00, a01), xA1 = cvt2(a10, a11);
        const unsigned xB0 = cvt2(b00, b01), xB1 = cvt2(b10, b11);
        const unsigned xC0 = cvt2(c00, c01), xC1 = cvt2(c10, c11);

        #pragma unroll 1
        for (int d = 0; d < D_F; d++) {
            const unsigned fbase = sbase + (unsigned)(d * 1024);

            // ================= layer 1 (f16 accum; bias via x k=3 column) =========
            unsigned w1h0, w1h1;
            ldsm2(w1h0, w1h1, fbase + lm_off);
            unsigned cA0[2], cA1[2], cB0[2], cB1[2], cC0[2], cC1[2];
            mma_k8_h(cA0, xA0, xA1, w1h0, 0u, 0u);
            mma_k8_h(cB0, xB0, xB1, w1h0, 0u, 0u);
            mma_k8_h(cC0, xC0, xC1, w1h0, 0u, 0u);
            mma_k8_h(cA1, xA0, xA1, w1h1, 0u, 0u);
            mma_k8_h(cB1, xB0, xB1, w1h1, 0u, 0u);
            mma_k8_h(cC1, xC0, xC1, w1h1, 0u, 0u);

            unsigned aA[4], aB[4], aC[4];
            aA[0] = relu2h(cA0[0]);  aA[1] = relu2h(cA0[1]);
            aA[2] = relu2h(cA1[0]);  aA[3] = relu2h(cA1[1]);
            aB[0] = relu2h(cB0[0]);  aB[1] = relu2h(cB0[1]);
            aB[2] = relu2h(cB1[0]);  aB[3] = relu2h(cB1[1]);
            aC[0] = relu2h(cC0[0]);  aC[1] = relu2h(cC0[1]);
            aC[2] = relu2h(cC1[0]);  aC[3] = relu2h(cC1[1]);

            // ================= layer 2 (f16 accum; pre-packed f16x2 bias) =========
            unsigned w2h0, w2h1, w2h2, w2h3;
            ldsm4(w2h0, w2h1, w2h2, w2h3, fbase + 256 + lm_off);
            const unsigned bh0 = sB2[d * 8 + q];
            const unsigned bh1 = sB2[d * 8 + 4 + q];

            unsigned eA0[2], eA1[2], eB0[2], eB1[2], eC0[2], eC1[2];
            mma_k16_h(eA0, aA, w2h0, w2h1, bh0, bh0);
            mma_k16_h(eB0, aB, w2h0, w2h1, bh0, bh0);
            mma_k16_h(eC0, aC, w2h0, w2h1, bh0, bh0);
            mma_k16_h(eA1, aA, w2h2, w2h3, bh1, bh1);
            mma_k16_h(eB1, aB, w2h2, w2h3, bh1, bh1);
            mma_k16_h(eC1, aC, w2h2, w2h3, bh1, bh1);

            unsigned gA[4], gB[4], gC[4];
            gA[0] = relu2h(eA0[0]);  gA[1] = relu2h(eA0[1]);
            gA[2] = relu2h(eA1[0]);  gA[3] = relu2h(eA1[1]);
            gB[0] = relu2h(eB0[0]);  gB[1] = relu2h(eB0[1]);
            gB[2] = relu2h(eB1[0]);  gB[3] = relu2h(eB1[1]);
            gC[0] = relu2h(eC0[0]);  gC[1] = relu2h(eC0[1]);
            gC[2] = relu2h(eC1[0]);  gC[3] = relu2h(eC1[1]);

            // ========== layer 3 TRANSPOSED: A=W3 (rows=o), B=g frags (cols=points) =
            // C: lane(q,r) holds (o=r, points 2q,2q+1) -> STG.64 per pair.
            unsigned w3t0, w3t1;
            ldsm2(w3t0, w3t1, fbase + 768 + lm_off);
            const unsigned w3a[4] = {w3t0, 0u, w3t1, 0u};   // o rows 8-15 zero
            const float bo = sB3[d * 8 + r];                // b3[d][o=r], 0-padded
            float* rp = out + (size_t)(d * 3 + r) * N;      // valid when r < 3

            float fL[4], fH[4];
            // sub-tile A
            mma_k16_z(fL, w3a, gA[0], gA[2]);
            mma_k16_z(fH, w3a, gA[1], gA[3]);
            if (t0) *(float2*)(rp + s0) = make_float2(fL[0] + bo, fL[1] + bo);
            if (t1) *(float2*)(rp + s1) = make_float2(fH[0] + bo, fH[1] + bo);
            // sub-tile B
            mma_k16_z(fL, w3a, gB[0], gB[2]);
            mma_k16_z(fH, w3a, gB[1], gB[3]);
            if (t2) *(float2*)(rp + s2) = make_float2(fL[0] + bo, fL[1] + bo);
            if (t3) *(float2*)(rp + s3) = make_float2(fH[0] + bo, fH[1] + bo);
            // sub-tile C
            mma_k16_z(fL, w3a, gC[0], gC[2]);
            mma_k16_z(fH, w3a, gC[1], gC[3]);
            if (t4) *(float2*)(rp + s4) = make_float2(fL[0] + bo, fL[1] + bo);
            if (t5) *(float2*)(rp + s5) = make_float2(fH[0] + bo, fH[1] + bo);
        }
    }
}

extern "C" void kernel_launch(void* const* d_in, const int* in_sizes, int n_in,
                              void* d_out, int out_size)
{
    const float* x  = (const float*)d_in[0];
    const float* W1 = (const float*)d_in[1];
    const float* b1 = (const float*)d_in[2];
    const float* W2 = (const float*)d_in[3];
    const float* b2 = (const float*)d_in[4];
    const float* W3 = (const float*)d_in[5];
    const float* b3 = (const float*)d_in[6];
    float* out = (float*)d_out;

    const int N = in_sizes[0] / 3;   // x is [1,3,N]

    prep_kernel<<<(8448 + 255) / 256, 256>>>(W1, b1, W2, b2, W3, b3);

    // 9 CTAs/SM x 128 threads on 152 SMs = 1368 CTAs, one clean wave
    fields_mma_kernel<<<1368, 128>>>(x, out, N);
}

// round 17
// speedup vs baseline: 1.1325x; 1.0031x over previous
#include <cuda_runtime.h>
#include <cuda_fp16.h>
#include <cstdint>

#define D_F 16

// ---- global prepped weight image (fp16, hi-only, compact) ----
// Per field d (1024 B at d*1024):
//   +0    : W1, 2 tiles 8x8 f16 [n0-7][n8-15]; row=n, col=k: k<3 -> W1[d][n][k],
//           k==3 -> b1[d][n], else 0
//   +256  : W2, 4 tiles {(n0,k0),(n0,k1),(n1,k0),(n1,k1)}; W2[d][g][h]
//   +768  : W3, 2 tiles [k0][k1]; row=o (0 pad o>=3), col=h   (used as A of l3)
// B2 at 16384: u32[16][8]  packed f16x2 pairs (b2[d][2j], b2[d][2j+1])
// B3 at 16896: f32[16][8]  b3[d][o] (0 pad o>=3)
#define B2_OFF 16384
#define B3_OFF 16896
#define IMG_BYTES 17408

__device__ __align__(16) unsigned char g_img[IMG_BYTES];

// ============ prep kernel ============
__global__ void prep_kernel(const float* __restrict__ W1, const float* __restrict__ b1,
                            const float* __restrict__ W2, const float* __restrict__ b2,
                            const float* __restrict__ W3, const float* __restrict__ b3)
{
    int i = blockIdx.x * blockDim.x + threadIdx.x;
    unsigned short* wimg = (unsigned short*)g_img;
    if (i < 8192) {                       // 16 fields x 512 hi entries
        int d = i >> 9;
        int w = i & 511;
        int fb = d * 512;
        float v = 0.0f;
        if (w < 128) {                    // W1 (+ b1 in k=3 column)
            int s = w, tile = s >> 6, rr = (s >> 3) & 7, cc = s & 7;
            int n = tile * 8 + rr;
            if (cc < 3)       v = W1[d * 48 + n * 3 + cc];
            else if (cc == 3) v = b1[d * 16 + n];
        } else if (w < 384) {             // W2
            int s = w - 128, tt = s >> 6, rr = (s >> 3) & 7, cc = s & 7;
            int nt = tt >> 1, kt = tt & 1;
            v = W2[d * 256 + (nt * 8 + rr) * 16 + (kt * 8 + cc)];
        } else {                          // W3
            int s = w - 384, kt = s >> 6, rr = (s >> 3) & 7, cc = s & 7;
            v = (rr < 3) ? W3[d * 48 + rr * 16 + (kt * 8 + cc)] : 0.0f;
        }
        __half hv = __float2half_rn(v);
        wimg[fb + w] = reinterpret_cast<unsigned short&>(hv);
    } else if (i < 8192 + 128) {          // b2 packed f16x2 pairs
        int j = i - 8192;
        int d = j >> 3, pr = j & 7;
        __half h0 = __float2half_rn(b2[d * 16 + 2 * pr]);
        __half h1 = __float2half_rn(b2[d * 16 + 2 * pr + 1]);
        unsigned u0 = reinterpret_cast<unsigned short&>(h0);
        unsigned u1 = reinterpret_cast<unsigned short&>(h1);
        ((unsigned*)(g_img + B2_OFF))[j] = u0 | (u1 << 16);
    } else if (i < 8192 + 128 + 128) {    // b3 padded f32
        int j = i - 8320;
        int d = j >> 3, o = j & 7;
        ((float*)(g_img + B3_OFF))[j] = (o < 3) ? b3[d * 3 + o] : 0.0f;
    }
}

// ============ mma / cvt helpers ============
__device__ __forceinline__ void ldsm4(unsigned& r0, unsigned& r1, unsigned& r2, unsigned& r3,
                                      unsigned a) {
    asm volatile("ldmatrix.sync.aligned.m8n8.x4.shared.b16 {%0,%1,%2,%3}, [%4];"
                 : "=r"(r0), "=r"(r1), "=r"(r2), "=r"(r3) : "r"(a));
}
__device__ __forceinline__ void ldsm2(unsigned& r0, unsigned& r1, unsigned a) {
    asm volatile("ldmatrix.sync.aligned.m8n8.x2.shared.b16 {%0,%1}, [%2];"
                 : "=r"(r0), "=r"(r1) : "r"(a));
}
// f16-accumulator m16n8k8
__device__ __forceinline__ void mma_k8_h(unsigned d[2], unsigned a0, unsigned a1, unsigned b0,
                                         unsigned c0, unsigned c1) {
    asm volatile("mma.sync.aligned.m16n8k8.row.col.f16.f16.f16.f16 "
                 "{%0,%1}, {%2,%3}, {%4}, {%5,%6};"
                 : "=r"(d[0]), "=r"(d[1])
                 : "r"(a0), "r"(a1), "r"(b0), "r"(c0), "r"(c1));
}
// f16-accumulator m16n8k16
__device__ __forceinline__ void mma_k16_h(unsigned d[2], const unsigned a[4],
                                          unsigned b0, unsigned b1,
                                          unsigned c0, unsigned c1) {
    asm volatile("mma.sync.aligned.m16n8k16.row.col.f16.f16.f16.f16 "
                 "{%0,%1}, {%2,%3,%4,%5}, {%6,%7}, {%8,%9};"
                 : "=r"(d[0]), "=r"(d[1])
                 : "r"(a[0]), "r"(a[1]), "r"(a[2]), "r"(a[3]),
                   "r"(b0), "r"(b1), "r"(c0), "r"(c1));
}
// f32-accumulator m16n8k16, C = 0 (layer 3 transposed; bias added after)
__device__ __forceinline__ void mma_k16_z(float d[4], const unsigned a[4],
                                          unsigned b0, unsigned b1) {
    asm volatile("mma.sync.aligned.m16n8k16.row.col.f32.f16.f16.f32 "
                 "{%0,%1,%2,%3}, {%4,%5,%6,%7}, {%8,%9}, {%10,%11,%12,%13};"
                 : "=f"(d[0]), "=f"(d[1]), "=f"(d[2]), "=f"(d[3])
                 : "r"(a[0]), "r"(a[1]), "r"(a[2]), "r"(a[3]), "r"(b0), "r"(b1),
                   "f"(0.0f), "f"(0.0f), "f"(0.0f), "f"(0.0f));
}
__device__ __forceinline__ unsigned cvt2(float v0, float v1) {
    unsigned h;
    asm("cvt.rn.f16x2.f32 %0, %1, %2;" : "=r"(h) : "f"(v1), "f"(v0));
    return h;
}
__device__ __forceinline__ unsigned relu2h(unsigned v) {
    unsigned r;
    asm("max.f16x2 %0, %1, %2;" : "=r"(r) : "r"(v), "r"(0u));
    return r;
}

// ============ main kernel: 3 point-tiles (48 pts), transposed l3, STG.128 ============
// Point permutation: fragment row m holds point perm(m) = (m&~1)*2 + (m&1) (+2 for
// rows 8-15). This makes l3-C lane(q,r) own points 4q..4q+3 -> one float4 store.
__global__ __launch_bounds__(128, 9)
void fields_mma_kernel(const float* __restrict__ x, float* __restrict__ out, int N)
{
    __shared__ __align__(16) unsigned char smem[IMG_BYTES];
    {
        const uint4* src = (const uint4*)g_img;
        uint4* dst = (uint4*)smem;
        for (int i = threadIdx.x; i < IMG_BYTES / 16; i += blockDim.x) dst[i] = src[i];
    }
    __syncthreads();

    const unsigned sbase = (unsigned)__cvta_generic_to_shared(smem);
    const unsigned* sB2 = (const unsigned*)(smem + B2_OFF);
    const float*    sB3 = (const float*)(smem + B3_OFF);

    const int tid  = threadIdx.x;
    const int wid  = tid >> 5, lane = tid & 31;
    const int q    = lane & 3, r = lane >> 2;
    const unsigned lm_off = ((unsigned)(lane >> 3) << 7) + ((unsigned)(lane & 7) << 4);

    // permuted point offset for fragment rows r (low half) / r+8 (high half = +2)
    const int pr = ((r & 6) << 1) | (r & 1);   // {0,1,4,5,8,9,12,13}

    const int gwarp  = blockIdx.x * 4 + wid;
    const int nwarps = gridDim.x * 4;
    const int ntiles = (N + 47) / 48;            // 48 points per tile

    for (int tile = gwarp; tile < ntiles; tile += nwarps) {
        const int P = tile * 48;
        const int pA0 = P + pr,      pA1 = pA0 + 2;    // subtile A rows
        const int pB0 = pA0 + 16,    pB1 = pA0 + 18;
        const int pC0 = pA0 + 32,    pC1 = pA0 + 34;
        const bool iA0 = pA0 < N, iA1 = pA1 < N, iB0 = pB0 < N, iB1 = pB1 < N;
        const bool iC0 = pC0 < N, iC1 = pC1 < N;

        // ---- hoisted store offsets + guards (d-invariant, float4-aligned) ----
        const int sA = P + 4 * q, sB = sA + 16, sC = sA + 32;
        const bool wv = (r < 3);
        const bool tA = wv && (sA + 3 < N);
        const bool tB = wv && (sB + 3 < N);
        const bool tC = wv && (sC + 3 < N);

        // ---- x A-fragments (single fp16): k = {x0,x1,x2,1,0,0,0,0} ----
        float a00 = 0.f, a01 = 0.f, a10 = 0.f, a11 = 0.f;
        float b00 = 0.f, b01 = 0.f, b10 = 0.f, b11 = 0.f;
        float c00 = 0.f, c01 = 0.f, c10 = 0.f, c11 = 0.f;
        if (q == 0) {
            if (iA0) { a00 = x[pA0]; a01 = x[N + pA0]; }
            if (iA1) { a10 = x[pA1]; a11 = x[N + pA1]; }
            if (iB0) { b00 = x[pB0]; b01 = x[N + pB0]; }
            if (iB1) { b10 = x[pB1]; b11 = x[N + pB1]; }
            if (iC0) { c00 = x[pC0]; c01 = x[N + pC0]; }
            if (iC1) { c10 = x[pC1]; c11 = x[N + pC1]; }
        } else if (q == 1) {
            if (iA0) { a00 = x[2 * N + pA0]; a01 = 1.0f; }
            if (iA1) { a10 = x[2 * N + pA1]; a11 = 1.0f; }
            if (iB0) { b00 = x[2 * N + pB0]; b01 = 1.0f; }
            if (iB1) { b10 = x[2 * N + pB1]; b11 = 1.0f; }
            if (iC0) { c00 = x[2 * N + pC0]; c01 = 1.0f; }
            if (iC1) { c10 = x[2 * N + pC1]; c11 = 1.0f; }
        }
        const unsigned xA0 = cvt2(a00, a01), xA1 = cvt2(a10, a11);
        const unsigned xB0 = cvt2(b00, b01), xB1 = cvt2(b10, b11);
        const unsigned xC0 = cvt2(c00, c01), xC1 = cvt2(c10, c11);

        #pragma unroll 1
        for (int d = 0; d < D_F; d++) {
            const unsigned fbase = sbase + (unsigned)(d * 1024);

            // ================= layer 1 (f16 accum; bias via x k=3 column) =========
            unsigned w1h0, w1h1;
            ldsm2(w1h0, w1h1, fbase + lm_off);
            unsigned cA0[2], cA1[2], cB0[2], cB1[2], cC0[2], cC1[2];
            mma_k8_h(cA0, xA0, xA1, w1h0, 0u, 0u);
            mma_k8_h(cB0, xB0, xB1, w1h0, 0u, 0u);
            mma_k8_h(cC0, xC0, xC1, w1h0, 0u, 0u);
            mma_k8_h(cA1, xA0, xA1, w1h1, 0u, 0u);
            mma_k8_h(cB1, xB0, xB1, w1h1, 0u, 0u);
            mma_k8_h(cC1, xC0, xC1, w1h1, 0u, 0u);

            unsigned aA[4], aB[4], aC[4];
            aA[0] = relu2h(cA0[0]);  aA[1] = relu2h(cA0[1]);
            aA[2] = relu2h(cA1[0]);  aA[3] = relu2h(cA1[1]);
            aB[0] = relu2h(cB0[0]);  aB[1] = relu2h(cB0[1]);
            aB[2] = relu2h(cB1[0]);  aB[3] = relu2h(cB1[1]);
            aC[0] = relu2h(cC0[0]);  aC[1] = relu2h(cC0[1]);
            aC[2] = relu2h(cC1[0]);  aC[3] = relu2h(cC1[1]);

            // ================= layer 2 (f16 accum; pre-packed f16x2 bias) =========
            unsigned w2h0, w2h1, w2h2, w2h3;
            ldsm4(w2h0, w2h1, w2h2, w2h3, fbase + 256 + lm_off);
            const unsigned bh0 = sB2[d * 8 + q];
            const unsigned bh1 = sB2[d * 8 + 4 + q];

            unsigned eA0[2], eA1[2], eB0[2], eB1[2], eC0[2], eC1[2];
            mma_k16_h(eA0, aA, w2h0, w2h1, bh0, bh0);
            mma_k16_h(eB0, aB, w2h0, w2h1, bh0, bh0);
            mma_k16_h(eC0, aC, w2h0, w2h1, bh0, bh0);
            mma_k16_h(eA1, aA, w2h2, w2h3, bh1, bh1);
            mma_k16_h(eB1, aB, w2h2, w2h3, bh1, bh1);
            mma_k16_h(eC1, aC, w2h2, w2h3, bh1, bh1);

            unsigned gA[4], gB[4], gC[4];
            gA[0] = relu2h(eA0[0]);  gA[1] = relu2h(eA0[1]);
            gA[2] = relu2h(eA1[0]);  gA[3] = relu2h(eA1[1]);
            gB[0] = relu2h(eB0[0]);  gB[1] = relu2h(eB0[1]);
            gB[2] = relu2h(eB1[0]);  gB[3] = relu2h(eB1[1]);
            gC[0] = relu2h(eC0[0]);  gC[1] = relu2h(eC0[1]);
            gC[2] = relu2h(eC1[0]);  gC[3] = relu2h(eC1[1]);

            // ========== layer 3 TRANSPOSED: A=W3 (rows=o), B=g frags (cols=points) =
            // With the point permutation, lane(q,r) owns points 4q..4q+3 of row o=r:
            // fL[0],fL[1] = pts 4q,4q+1 ; fH[0],fH[1] = pts 4q+2,4q+3  -> STG.128.
            unsigned w3t0, w3t1;
            ldsm2(w3t0, w3t1, fbase + 768 + lm_off);
            const unsigned w3a[4] = {w3t0, 0u, w3t1, 0u};   // o rows 8-15 zero
            const float bo = sB3[d * 8 + r];                // b3[d][o=r], 0-padded
            float* rp = out + (size_t)(d * 3 + r) * N;      // valid when r < 3

            float fL[4], fH[4];
            // sub-tile A
            mma_k16_z(fL, w3a, gA[0], gA[2]);
            mma_k16_z(fH, w3a, gA[1], gA[3]);
            if (tA) *(float4*)(rp + sA) =
                make_float4(fL[0] + bo, fL[1] + bo, fH[0] + bo, fH[1] + bo);
            // sub-tile B
            mma_k16_z(fL, w3a, gB[0], gB[2]);
            mma_k16_z(fH, w3a, gB[1], gB[3]);
            if (tB) *(float4*)(rp + sB) =
                make_float4(fL[0] + bo, fL[1] + bo, fH[0] + bo, fH[1] + bo);
            // sub-tile C
            mma_k16_z(fL, w3a, gC[0], gC[2]);
            mma_k16_z(fH, w3a, gC[1], gC[3]);
            if (tC) *(float4*)(rp + sC) =
                make_float4(fL[0] + bo, fL[1] + bo, fH[0] + bo, fH[1] + bo);
        }
    }
}

extern "C" void kernel_launch(void* const* d_in, const int* in_sizes, int n_in,
                              void* d_out, int out_size)
{
    const float* x  = (const float*)d_in[0];
    const float* W1 = (const float*)d_in[1];
    const float* b1 = (const float*)d_in[2];
    const float* W2 = (const float*)d_in[3];
    const float* b2 = (const float*)d_in[4];
    const float* W3 = (const float*)d_in[5];
    const float* b3 = (const float*)d_in[6];
    float* out = (float*)d_out;

    const int N = in_sizes[0] / 3;   // x is [1,3,N]

    prep_kernel<<<(8448 + 255) / 256, 256>>>(W1, b1, W2, b2, W3, b3);

    // 9 CTAs/SM x 128 threads on 152 SMs = 1368 CTAs, one clean wave
    fields_mma_kernel<<<1368, 128>>>(x, out, N);
}